// round 3
// baseline (speedup 1.0000x reference)
#include <cuda_runtime.h>
#include <cstdint>

// ---------------------------------------------------------------------------
// HSLSTMRegressor: 2-layer LSTM (B=256, T=512, I=64, H=512) + linear head + MSE
// R3: 128 CTAs x 128 threads (4 warps), 32 rows/warp (2x B-fragment reuse),
//     software-pipelined recurrence: layer1(t) + layer0(t+1) share one h0 read
//     and ONE grid barrier per step. h stored pre-rounded to tf32 (no cvt in
//     h spans). Weights resident in SMEM (200KB tf32 fragments).
// ---------------------------------------------------------------------------

#define BATCH 256
#define TT    512
#define II    64
#define HH    512
#define NCTA  128
#define NTHREADS 128
#define NK16_0 36   // (64 + 512) / 16
#define NK16_1 64   // (512 + 512) / 16
#define SMEM_W0 (4 * NK16_0 * 32)          // uint4 elements, layer0 slice
#define SMEM_W1 (4 * NK16_1 * 32)          // uint4 elements, layer1 slice
#define SMEM_BYTES ((SMEM_W0 + SMEM_W1) * 16)

__device__ float g_h0[2][BATCH * HH];
__device__ float g_h1[2][BATCH * HH];
__device__ unsigned g_bar = 0;   // grid barrier counter (reset at kernel end)

__device__ __forceinline__ unsigned f2tf(float f) {
    unsigned u;
    asm("cvt.rna.tf32.f32 %0, %1;" : "=r"(u) : "f"(f));
    return u;
}

__device__ __forceinline__ void mma_tf32(float* c,
                                         unsigned a0, unsigned a1, unsigned a2, unsigned a3,
                                         unsigned b0, unsigned b1) {
    asm volatile(
        "mma.sync.aligned.m16n8k8.row.col.f32.tf32.tf32.f32 "
        "{%0,%1,%2,%3},{%4,%5,%6,%7},{%8,%9},{%0,%1,%2,%3};"
        : "+f"(c[0]), "+f"(c[1]), "+f"(c[2]), "+f"(c[3])
        : "r"(a0), "r"(a1), "r"(a2), "r"(a3), "r"(b0), "r"(b1));
}

__device__ __forceinline__ float sigf(float x) {
    return __fdividef(1.0f, 1.0f + __expf(-x));
}
__device__ __forceinline__ float tanh_(float x) {
    float e = __expf(-2.0f * fabsf(x));
    float r = __fdividef(1.0f - e, 1.0f + e);
    return copysignf(r, x);
}

__device__ __forceinline__ void gsync(unsigned& barn) {
    __threadfence();
    __syncthreads();
    if (threadIdx.x == 0) {
        atomicAdd(&g_bar, 1u);
        unsigned tgt = barn + (unsigned)gridDim.x;
        while (*(volatile unsigned*)&g_bar < tgt) {}
        __threadfence();
    }
    barn += (unsigned)gridDim.x;
    __syncthreads();
}

struct Frag {
    unsigned a[4], b[4], c[4], d[4];
};

template <bool CVT>
__device__ __forceinline__ Frag cvt_frag(float4 va, float4 vb, float4 vc, float4 vd) {
    Frag f;
    if (CVT) {
        f.a[0] = f2tf(va.x); f.a[1] = f2tf(va.y); f.a[2] = f2tf(va.z); f.a[3] = f2tf(va.w);
        f.b[0] = f2tf(vb.x); f.b[1] = f2tf(vb.y); f.b[2] = f2tf(vb.z); f.b[3] = f2tf(vb.w);
        f.c[0] = f2tf(vc.x); f.c[1] = f2tf(vc.y); f.c[2] = f2tf(vc.z); f.c[3] = f2tf(vc.w);
        f.d[0] = f2tf(vd.x); f.d[1] = f2tf(vd.y); f.d[2] = f2tf(vd.z); f.d[3] = f2tf(vd.w);
    } else {
        f.a[0] = __float_as_uint(va.x); f.a[1] = __float_as_uint(va.y);
        f.a[2] = __float_as_uint(va.z); f.a[3] = __float_as_uint(va.w);
        f.b[0] = __float_as_uint(vb.x); f.b[1] = __float_as_uint(vb.y);
        f.b[2] = __float_as_uint(vb.z); f.b[3] = __float_as_uint(vb.w);
        f.c[0] = __float_as_uint(vc.x); f.c[1] = __float_as_uint(vc.y);
        f.c[2] = __float_as_uint(vc.z); f.c[3] = __float_as_uint(vc.w);
        f.d[0] = __float_as_uint(vd.x); f.d[1] = __float_as_uint(vd.y);
        f.d[2] = __float_as_uint(vd.z); f.d[3] = __float_as_uint(vd.w);
    }
    return f;
}

__device__ __forceinline__ void mma_gate(float* acc8, const Frag& f, uint4 q) {
    mma_tf32(acc8 + 0, f.a[0], f.b[0], f.a[1], f.b[1], q.x, q.y);
    mma_tf32(acc8 + 0, f.a[2], f.b[2], f.a[3], f.b[3], q.z, q.w);
    mma_tf32(acc8 + 4, f.c[0], f.d[0], f.c[1], f.d[1], q.x, q.y);
    mma_tf32(acc8 + 4, f.c[2], f.d[2], f.c[3], f.d[3], q.z, q.w);
}

// Plain span: nblk k16 blocks; weights sW[(g*WSTRIDE + kkW + j)*32] (sW has +lane).
// Act rows pA..pD advance 16 floats per block. Depth-2 prefetch on the L2 stream.
template <int WSTRIDE, bool CVT>
__device__ __forceinline__ void span(float acc[4][8], const uint4* __restrict__ sW,
                                     int kkW, int nblk,
                                     const float* __restrict__ pA, const float* __restrict__ pB,
                                     const float* __restrict__ pC, const float* __restrict__ pD) {
    float4 a0 = __ldcg((const float4*)pA), b0 = __ldcg((const float4*)pB);
    float4 c0 = __ldcg((const float4*)pC), d0 = __ldcg((const float4*)pD);
    const int j1 = (nblk > 1) ? 1 : 0;
    float4 a1 = __ldcg((const float4*)(pA + j1 * 16)), b1 = __ldcg((const float4*)(pB + j1 * 16));
    float4 c1 = __ldcg((const float4*)(pC + j1 * 16)), d1 = __ldcg((const float4*)(pD + j1 * 16));
#pragma unroll 4
    for (int j = 0; j < nblk; ++j) {
        uint4 q0 = sW[(0 * WSTRIDE + kkW + j) * 32];
        uint4 q1 = sW[(1 * WSTRIDE + kkW + j) * 32];
        uint4 q2 = sW[(2 * WSTRIDE + kkW + j) * 32];
        uint4 q3 = sW[(3 * WSTRIDE + kkW + j) * 32];
        const int jn = (j + 2 < nblk) ? (j + 2) : (nblk - 1);
        float4 na = __ldcg((const float4*)(pA + jn * 16)), nb = __ldcg((const float4*)(pB + jn * 16));
        float4 nc = __ldcg((const float4*)(pC + jn * 16)), nd = __ldcg((const float4*)(pD + jn * 16));
        Frag f = cvt_frag<CVT>(a0, b0, c0, d0);
        mma_gate(acc[0], f, q0);
        mma_gate(acc[1], f, q1);
        mma_gate(acc[2], f, q2);
        mma_gate(acc[3], f, q3);
        a0 = a1; b0 = b1; c0 = c1; d0 = d1;
        a1 = na; b1 = nb; c1 = nc; d1 = nd;
    }
}

// Fused span over the shared h0 stream (32 blocks): one act load feeds both
// layer1 (W1 blocks j) and layer0 (W0 blocks j+4).
__device__ __forceinline__ void fused_span(float acc1[4][8], float acc0[4][8],
                                           const uint4* __restrict__ sW1,
                                           const uint4* __restrict__ sW0,
                                           const float* __restrict__ pA, const float* __restrict__ pB,
                                           const float* __restrict__ pC, const float* __restrict__ pD) {
    float4 a0 = __ldcg((const float4*)pA), b0 = __ldcg((const float4*)pB);
    float4 c0 = __ldcg((const float4*)pC), d0 = __ldcg((const float4*)pD);
    float4 a1 = __ldcg((const float4*)(pA + 16)), b1 = __ldcg((const float4*)(pB + 16));
    float4 c1 = __ldcg((const float4*)(pC + 16)), d1 = __ldcg((const float4*)(pD + 16));
#pragma unroll 2
    for (int j = 0; j < 32; ++j) {
        uint4 p0 = sW1[(0 * NK16_1 + j) * 32];
        uint4 p1 = sW1[(1 * NK16_1 + j) * 32];
        uint4 p2 = sW1[(2 * NK16_1 + j) * 32];
        uint4 p3 = sW1[(3 * NK16_1 + j) * 32];
        uint4 q0 = sW0[(0 * NK16_0 + 4 + j) * 32];
        uint4 q1 = sW0[(1 * NK16_0 + 4 + j) * 32];
        uint4 q2 = sW0[(2 * NK16_0 + 4 + j) * 32];
        uint4 q3 = sW0[(3 * NK16_0 + 4 + j) * 32];
        const int jn = (j + 2 < 32) ? (j + 2) : 31;
        float4 na = __ldcg((const float4*)(pA + jn * 16)), nb = __ldcg((const float4*)(pB + jn * 16));
        float4 nc = __ldcg((const float4*)(pC + jn * 16)), nd = __ldcg((const float4*)(pD + jn * 16));
        Frag f = cvt_frag<false>(a0, b0, c0, d0);
        mma_gate(acc1[0], f, p0);
        mma_gate(acc1[1], f, p1);
        mma_gate(acc1[2], f, p2);
        mma_gate(acc1[3], f, p3);
        mma_gate(acc0[0], f, q0);
        mma_gate(acc0[1], f, q1);
        mma_gate(acc0[2], f, q2);
        mma_gate(acc0[3], f, q3);
        a0 = a1; b0 = b1; c0 = c1; d0 = d1;
        a1 = na; b1 = nb; c1 = nc; d1 = nd;
    }
}

// rows4 = {rA, rB, rC, rD} global row indices; h stored pre-rounded to tf32.
__device__ __forceinline__ void cell_update(float acc[4][8],
                                            const float* __restrict__ bias8,
                                            float* __restrict__ creg,
                                            float* __restrict__ hout,
                                            const int* rows4, int cA) {
#pragma unroll
    for (int h = 0; h < 4; ++h) {
        int r = rows4[h];
        float2 hv;
#pragma unroll
        for (int q = 0; q < 2; ++q) {
            int p = h * 2 + q;
            float gi = acc[0][p] + bias8[0 + q];
            float gf = acc[1][p] + bias8[2 + q];
            float gg = acc[2][p] + bias8[4 + q];
            float go = acc[3][p] + bias8[6 + q];
            float cn = sigf(gf) * creg[p] + sigf(gi) * tanh_(gg);
            creg[p] = cn;
            float hv1 = sigf(go) * tanh_(cn);
            if (q == 0) hv.x = __uint_as_float(f2tf(hv1));
            else        hv.y = __uint_as_float(f2tf(hv1));
        }
        __stcg((float2*)&hout[r * HH + cA], hv);
    }
}

__global__ void __launch_bounds__(NTHREADS, 1)
lstm_kernel(const float* __restrict__ x, const float* __restrict__ y,
            const float* __restrict__ Wih0, const float* __restrict__ Whh0,
            const float* __restrict__ bih0, const float* __restrict__ bhh0,
            const float* __restrict__ Wih1, const float* __restrict__ Whh1,
            const float* __restrict__ bih1, const float* __restrict__ bhh1,
            const float* __restrict__ Wlin, const float* __restrict__ blin,
            float* __restrict__ dout, int out_size) {
    extern __shared__ uint4 smw[];
    uint4* sW0base = smw;
    uint4* sW1base = smw + SMEM_W0;

    const int tid = threadIdx.x;
    const int gtid = blockIdx.x * NTHREADS + tid;
    const int GSTRIDE = NCTA * NTHREADS;

    const int lane = tid & 31;
    const int w = tid >> 5;            // 0..3
    const int grp = lane >> 2;
    const int tig = lane & 3;
    const int mtile = blockIdx.x >> 6; // 0..1
    const int ub = blockIdx.x & 63;    // 0..63
    const int m0 = mtile * 128;
    const int u0 = ub * 8;
    const int rA = m0 + w * 32 + grp;  // rows rA, +8, +16, +24
    const int cA = u0 + 2 * tig;
    const int rows4[4] = {rA, rA + 8, rA + 16, rA + 24};

    // ------------- prologue: pack this CTA's weight slice into SMEM ---------
    for (int s = tid; s < SMEM_W0; s += NTHREADS) {
        int ln = s & 31;
        int kk = (s >> 5) % NK16_0;
        int g = s / (32 * NK16_0);
        int n = g * HH + u0 + (ln >> 2);
        int k = kk * 16 + (ln & 3) * 4;
        float v[4];
#pragma unroll
        for (int j = 0; j < 4; ++j) {
            int kj = k + j;
            v[j] = (kj < II) ? __ldg(&Wih0[n * II + kj]) : __ldg(&Whh0[n * HH + (kj - II)]);
        }
        sW0base[s] = make_uint4(f2tf(v[0]), f2tf(v[1]), f2tf(v[2]), f2tf(v[3]));
    }
    for (int s = tid; s < SMEM_W1; s += NTHREADS) {
        int ln = s & 31;
        int kk = (s >> 5) % NK16_1;
        int g = s / (32 * NK16_1);
        int n = g * HH + u0 + (ln >> 2);
        int k = kk * 16 + (ln & 3) * 4;
        float v[4];
#pragma unroll
        for (int j = 0; j < 4; ++j) {
            int kj = k + j;
            v[j] = (kj < HH) ? __ldg(&Wih1[n * HH + kj]) : __ldg(&Whh1[n * HH + (kj - HH)]);
        }
        sW1base[s] = make_uint4(f2tf(v[0]), f2tf(v[1]), f2tf(v[2]), f2tf(v[3]));
    }
    for (int i = gtid; i < BATCH * HH; i += GSTRIDE) {
        g_h0[0][i] = 0.0f;
        g_h1[0][i] = 0.0f;
    }

    float bias8_0[8], bias8_1[8];
#pragma unroll
    for (int g = 0; g < 4; ++g)
#pragma unroll
        for (int q = 0; q < 2; ++q) {
            int n = g * HH + cA + q;
            bias8_0[g * 2 + q] = __ldg(&bih0[n]) + __ldg(&bhh0[n]);
            bias8_1[g * 2 + q] = __ldg(&bih1[n]) + __ldg(&bhh1[n]);
        }

    const uint4* sW0 = sW0base + lane;
    const uint4* sW1 = sW1base + lane;

    float* h0_cur = g_h0[1];
    float* h0_nxt = g_h0[0];
    float* h1_prv = g_h1[0];
    float* h1_cur = g_h1[1];

    float c0reg[8] = {0.f, 0.f, 0.f, 0.f, 0.f, 0.f, 0.f, 0.f};
    float c1reg[8] = {0.f, 0.f, 0.f, 0.f, 0.f, 0.f, 0.f, 0.f};

    const int xoff = tig * 4;
    const float* xA = x + (size_t)rows4[0] * (TT * II) + xoff;
    const float* xB = x + (size_t)rows4[1] * (TT * II) + xoff;
    const float* xC = x + (size_t)rows4[2] * (TT * II) + xoff;
    const float* xD = x + (size_t)rows4[3] * (TT * II) + xoff;
    const int oA = rows4[0] * HH + xoff;
    const int oB = rows4[1] * HH + xoff;
    const int oC = rows4[2] * HH + xoff;
    const int oD = rows4[3] * HH + xoff;

    unsigned barn = 0;
    gsync(barn);   // prologue visibility (smem pack local; h zeros global)

    // ---- layer0(0): h0(0) = cell(x(0), h0=0) -> h0_cur -----------------------
    {
        float acc0[4][8];
#pragma unroll
        for (int a = 0; a < 4; ++a)
#pragma unroll
            for (int b = 0; b < 8; ++b) acc0[a][b] = 0.0f;
        span<NK16_0, true>(acc0, sW0, 0, 4, xA, xB, xC, xD);
        span<NK16_0, false>(acc0, sW0, 4, 32, g_h0[0] + oA, g_h0[0] + oB,
                            g_h0[0] + oC, g_h0[0] + oD);
        cell_update(acc0, bias8_0, c0reg, h0_cur, rows4, cA);
    }
    gsync(barn);

    // ---- main loop: iteration t computes layer1(t) and layer0(t+1) ----------
    for (int t = 0; t < TT; ++t) {
        float acc1[4][8], acc0[4][8];
#pragma unroll
        for (int a = 0; a < 4; ++a)
#pragma unroll
            for (int b = 0; b < 8; ++b) { acc1[a][b] = 0.0f; acc0[a][b] = 0.0f; }

        // shared h0(t) stream -> layer1 K[0:512) and layer0 h-part
        fused_span(acc1, acc0, sW1, sW0,
                   h0_cur + oA, h0_cur + oB, h0_cur + oC, h0_cur + oD);
        // layer1 K[512:1024): h1(t-1)
        span<NK16_1, false>(acc1, sW1, 32, 32,
                            h1_prv + oA, h1_prv + oB, h1_prv + oC, h1_prv + oD);
        cell_update(acc1, bias8_1, c1reg, h1_cur, rows4, cA);

        // layer0 x-part: x(t+1) (t=TT-1 recomputes x(TT-1); result unused)
        const int xt = (t < TT - 1) ? (t + 1) : (TT - 1);
        span<NK16_0, true>(acc0, sW0, 0, 4,
                           xA + xt * II, xB + xt * II, xC + xt * II, xD + xt * II);
        cell_update(acc0, bias8_0, c0reg, h0_nxt, rows4, cA);

        if (t < TT - 1) gsync(barn);

        float* tmp = h0_cur; h0_cur = h0_nxt; h0_nxt = tmp;
        tmp = h1_prv; h1_prv = h1_cur; h1_cur = tmp;
    }

    // ---------------- final barrier: non-zero CTAs arrive and exit ----------
    __threadfence();
    __syncthreads();
    if (tid == 0) atomicAdd(&g_bar, 1u);
    barn += NCTA;
    if (blockIdx.x != 0) return;

    if (tid == 0) {
        while (*(volatile unsigned*)&g_bar < barn) {}
        __threadfence();
        *(volatile unsigned*)&g_bar = 0u;  // reset for next graph replay
    }
    __syncthreads();

    // ---------------- epilogue on CTA 0: linear head + MSE loss --------------
    // final h1 = h1_prv (swapped after last iteration)
    const float* h1fin = h1_prv;
    float s0 = __ldg(&blin[0]);
    float s1 = __ldg(&blin[0]);
    const float* hr0 = h1fin + (size_t)tid * HH;
    const float* hr1 = h1fin + (size_t)(tid + 128) * HH;
#pragma unroll 4
    for (int c2 = 0; c2 < HH; c2 += 4) {
        float4 wv = __ldg((const float4*)(Wlin + c2));
        float4 h4 = __ldcg((const float4*)(hr0 + c2));
        float4 g4 = __ldcg((const float4*)(hr1 + c2));
        s0 += h4.x * wv.x + h4.y * wv.y + h4.z * wv.z + h4.w * wv.w;
        s1 += g4.x * wv.x + g4.y * wv.y + g4.z * wv.z + g4.w * wv.w;
    }

    __shared__ float red[NTHREADS];
    float d0 = s0 - __ldg(&y[tid]);
    float d1 = s1 - __ldg(&y[tid + 128]);
    red[tid] = d0 * d0 + d1 * d1;
    __syncthreads();
#pragma unroll
    for (int off = 64; off > 0; off >>= 1) {
        if (tid < off) red[tid] += red[tid + off];
        __syncthreads();
    }
    float loss = red[0] * (1.0f / BATCH);

    if (out_size >= BATCH + 1) {
        dout[tid] = s0;
        dout[tid + 128] = s1;
        if (tid == 0) dout[BATCH] = loss;
        for (int i2 = BATCH + 1 + tid; i2 < out_size; i2 += NTHREADS) dout[i2] = 0.0f;
    } else if (out_size == BATCH) {
        dout[tid] = s0;
        dout[tid + 128] = s1;
    } else if (out_size == 1) {
        if (tid == 0) dout[0] = loss;
    } else {
        if (tid < out_size) dout[tid] = s0;
        if (tid + 128 < out_size) dout[tid + 128] = s1;
    }
}

extern "C" void kernel_launch(void* const* d_in, const int* in_sizes, int n_in,
                              void* d_out, int out_size) {
    const float* x    = (const float*)d_in[0];
    const float* y    = (const float*)d_in[1];
    const float* Wih0 = (const float*)d_in[2];
    const float* Whh0 = (const float*)d_in[3];
    const float* bih0 = (const float*)d_in[4];
    const float* bhh0 = (const float*)d_in[5];
    const float* Wih1 = (const float*)d_in[6];
    const float* Whh1 = (const float*)d_in[7];
    const float* bih1 = (const float*)d_in[8];
    const float* bhh1 = (const float*)d_in[9];
    const float* Wlin = (const float*)d_in[10];
    const float* blin = (const float*)d_in[11];

    cudaFuncSetAttribute(lstm_kernel, cudaFuncAttributeMaxDynamicSharedMemorySize,
                         SMEM_BYTES);
    lstm_kernel<<<NCTA, NTHREADS, SMEM_BYTES>>>(x, y, Wih0, Whh0, bih0, bhh0,
                                                Wih1, Whh1, bih1, bhh1, Wlin, blin,
                                                (float*)d_out, out_size);
}

// round 4
// speedup vs baseline: 1.2847x; 1.2847x over previous
#include <cuda_runtime.h>
#include <cstdint>

// ---------------------------------------------------------------------------
// HSLSTMRegressor: 2-layer LSTM (B=256, T=512, I=64, H=512) + linear head + MSE
// R4: 128 CTAs x 256 threads (8 warps = 4 row-tiles x 2 k-halves).
//     - 32 rows/warp (4x weight-LDS reuse, same as R3)
//     - split-K across warp pairs, smem reduction -> 2 warps/SMSP latency hiding
//     - fused h0 span: layer1(t) + layer0(t+1) share one h0 read, 1 barrier/step
//     - h stored pre-rounded tf32; weights resident in SMEM (200KB)
// ---------------------------------------------------------------------------

#define BATCH 256
#define TT    512
#define II    64
#define HH    512
#define NCTA  128
#define NTHREADS 256
#define NK16_0 36   // (64 + 512) / 16
#define NK16_1 64   // (512 + 512) / 16
#define SMEM_W0 (4 * NK16_0 * 32)          // uint4 elements, layer0 slice
#define SMEM_W1 (4 * NK16_1 * 32)          // uint4 elements, layer1 slice
#define SMEM_WBYTES ((SMEM_W0 + SMEM_W1) * 16)
#define SMEM_RED_FLOATS (4 * 32 * 32)      // [chunk i4][rt][lane] float4-chunked
#define SMEM_BYTES (SMEM_WBYTES + SMEM_RED_FLOATS * 4)

__device__ float g_h0[2][BATCH * HH];
__device__ float g_h1[2][BATCH * HH];
__device__ unsigned g_bar = 0;   // grid barrier counter (reset at kernel end)

__device__ __forceinline__ unsigned f2tf(float f) {
    unsigned u;
    asm("cvt.rna.tf32.f32 %0, %1;" : "=r"(u) : "f"(f));
    return u;
}

__device__ __forceinline__ void mma_tf32(float* c,
                                         unsigned a0, unsigned a1, unsigned a2, unsigned a3,
                                         unsigned b0, unsigned b1) {
    asm volatile(
        "mma.sync.aligned.m16n8k8.row.col.f32.tf32.tf32.f32 "
        "{%0,%1,%2,%3},{%4,%5,%6,%7},{%8,%9},{%0,%1,%2,%3};"
        : "+f"(c[0]), "+f"(c[1]), "+f"(c[2]), "+f"(c[3])
        : "r"(a0), "r"(a1), "r"(a2), "r"(a3), "r"(b0), "r"(b1));
}

__device__ __forceinline__ float sigf(float x) {
    return __fdividef(1.0f, 1.0f + __expf(-x));
}
__device__ __forceinline__ float tanh_(float x) {
    float e = __expf(-2.0f * fabsf(x));
    float r = __fdividef(1.0f - e, 1.0f + e);
    return copysignf(r, x);
}

__device__ __forceinline__ void gsync(unsigned& barn) {
    __threadfence();
    __syncthreads();
    if (threadIdx.x == 0) {
        atomicAdd(&g_bar, 1u);
        unsigned tgt = barn + (unsigned)gridDim.x;
        while (*(volatile unsigned*)&g_bar < tgt) {}
        __threadfence();
    }
    barn += (unsigned)gridDim.x;
    __syncthreads();
}

struct Frag {
    unsigned a[4], b[4], c[4], d[4];
};

template <bool CVT>
__device__ __forceinline__ Frag cvt_frag(float4 va, float4 vb, float4 vc, float4 vd) {
    Frag f;
    if (CVT) {
        f.a[0] = f2tf(va.x); f.a[1] = f2tf(va.y); f.a[2] = f2tf(va.z); f.a[3] = f2tf(va.w);
        f.b[0] = f2tf(vb.x); f.b[1] = f2tf(vb.y); f.b[2] = f2tf(vb.z); f.b[3] = f2tf(vb.w);
        f.c[0] = f2tf(vc.x); f.c[1] = f2tf(vc.y); f.c[2] = f2tf(vc.z); f.c[3] = f2tf(vc.w);
        f.d[0] = f2tf(vd.x); f.d[1] = f2tf(vd.y); f.d[2] = f2tf(vd.z); f.d[3] = f2tf(vd.w);
    } else {
        f.a[0] = __float_as_uint(va.x); f.a[1] = __float_as_uint(va.y);
        f.a[2] = __float_as_uint(va.z); f.a[3] = __float_as_uint(va.w);
        f.b[0] = __float_as_uint(vb.x); f.b[1] = __float_as_uint(vb.y);
        f.b[2] = __float_as_uint(vb.z); f.b[3] = __float_as_uint(vb.w);
        f.c[0] = __float_as_uint(vc.x); f.c[1] = __float_as_uint(vc.y);
        f.c[2] = __float_as_uint(vc.z); f.c[3] = __float_as_uint(vc.w);
        f.d[0] = __float_as_uint(vd.x); f.d[1] = __float_as_uint(vd.y);
        f.d[2] = __float_as_uint(vd.z); f.d[3] = __float_as_uint(vd.w);
    }
    return f;
}

__device__ __forceinline__ void mma_gate(float* acc8, const Frag& f, uint4 q) {
    mma_tf32(acc8 + 0, f.a[0], f.b[0], f.a[1], f.b[1], q.x, q.y);
    mma_tf32(acc8 + 0, f.a[2], f.b[2], f.a[3], f.b[3], q.z, q.w);
    mma_tf32(acc8 + 4, f.c[0], f.d[0], f.c[1], f.d[1], q.x, q.y);
    mma_tf32(acc8 + 4, f.c[2], f.d[2], f.c[3], f.d[3], q.z, q.w);
}

// Span over NBLK k16 blocks. Weights at sW[(g*WSTRIDE + wblk0 + j)*32]
// (sW already +lane). Acts advance 16 floats/block from the given pointers.
template <int WSTRIDE, bool CVT, int NBLK>
__device__ __forceinline__ void span(float acc[4][8], const uint4* __restrict__ sW,
                                     int wblk0,
                                     const float* __restrict__ pA, const float* __restrict__ pB,
                                     const float* __restrict__ pC, const float* __restrict__ pD) {
    float4 a0 = __ldcg((const float4*)pA), b0 = __ldcg((const float4*)pB);
    float4 c0 = __ldcg((const float4*)pC), d0 = __ldcg((const float4*)pD);
    const int j1 = (NBLK > 1) ? 1 : 0;
    float4 a1 = __ldcg((const float4*)(pA + j1 * 16)), b1 = __ldcg((const float4*)(pB + j1 * 16));
    float4 c1 = __ldcg((const float4*)(pC + j1 * 16)), d1 = __ldcg((const float4*)(pD + j1 * 16));
#pragma unroll 4
    for (int j = 0; j < NBLK; ++j) {
        uint4 q0 = sW[(0 * WSTRIDE + wblk0 + j) * 32];
        uint4 q1 = sW[(1 * WSTRIDE + wblk0 + j) * 32];
        uint4 q2 = sW[(2 * WSTRIDE + wblk0 + j) * 32];
        uint4 q3 = sW[(3 * WSTRIDE + wblk0 + j) * 32];
        const int jn = (j + 2 < NBLK) ? (j + 2) : (NBLK - 1);
        float4 na = __ldcg((const float4*)(pA + jn * 16)), nb = __ldcg((const float4*)(pB + jn * 16));
        float4 nc = __ldcg((const float4*)(pC + jn * 16)), nd = __ldcg((const float4*)(pD + jn * 16));
        Frag f = cvt_frag<CVT>(a0, b0, c0, d0);
        mma_gate(acc[0], f, q0);
        mma_gate(acc[1], f, q1);
        mma_gate(acc[2], f, q2);
        mma_gate(acc[3], f, q3);
        a0 = a1; b0 = b1; c0 = c1; d0 = d1;
        a1 = na; b1 = nb; c1 = nc; d1 = nd;
    }
}

// Fused span over 16 shared-h0 blocks: feeds acc1 (W1 block wb1+j) and
// acc0 (W0 block wb0+j) from one act stream.
__device__ __forceinline__ void fused_span(float acc1[4][8], float acc0[4][8],
                                           const uint4* __restrict__ sW1,
                                           const uint4* __restrict__ sW0,
                                           int wb1, int wb0,
                                           const float* __restrict__ pA, const float* __restrict__ pB,
                                           const float* __restrict__ pC, const float* __restrict__ pD) {
    float4 a0 = __ldcg((const float4*)pA), b0 = __ldcg((const float4*)pB);
    float4 c0 = __ldcg((const float4*)pC), d0 = __ldcg((const float4*)pD);
    float4 a1 = __ldcg((const float4*)(pA + 16)), b1 = __ldcg((const float4*)(pB + 16));
    float4 c1 = __ldcg((const float4*)(pC + 16)), d1 = __ldcg((const float4*)(pD + 16));
#pragma unroll 2
    for (int j = 0; j < 16; ++j) {
        uint4 p0 = sW1[(0 * NK16_1 + wb1 + j) * 32];
        uint4 p1 = sW1[(1 * NK16_1 + wb1 + j) * 32];
        uint4 p2 = sW1[(2 * NK16_1 + wb1 + j) * 32];
        uint4 p3 = sW1[(3 * NK16_1 + wb1 + j) * 32];
        uint4 q0 = sW0[(0 * NK16_0 + wb0 + j) * 32];
        uint4 q1 = sW0[(1 * NK16_0 + wb0 + j) * 32];
        uint4 q2 = sW0[(2 * NK16_0 + wb0 + j) * 32];
        uint4 q3 = sW0[(3 * NK16_0 + wb0 + j) * 32];
        const int jn = (j + 2 < 16) ? (j + 2) : 15;
        float4 na = __ldcg((const float4*)(pA + jn * 16)), nb = __ldcg((const float4*)(pB + jn * 16));
        float4 nc = __ldcg((const float4*)(pC + jn * 16)), nd = __ldcg((const float4*)(pD + jn * 16));
        Frag f = cvt_frag<false>(a0, b0, c0, d0);
        mma_gate(acc1[0], f, p0);
        mma_gate(acc1[1], f, p1);
        mma_gate(acc1[2], f, p2);
        mma_gate(acc1[3], f, p3);
        mma_gate(acc0[0], f, q0);
        mma_gate(acc0[1], f, q1);
        mma_gate(acc0[2], f, q2);
        mma_gate(acc0[3], f, q3);
        a0 = a1; b0 = b1; c0 = c1; d0 = d1;
        a1 = na; b1 = nb; c1 = nc; d1 = nd;
    }
}

// ---- split-K reduction through smem: layout [i4][rt][lane] of float4 --------
__device__ __forceinline__ void red_store(const float acc[4][8], float4* sred,
                                          int rt, int lane) {
    const float* a = &acc[0][0];
#pragma unroll
    for (int i4 = 0; i4 < 8; ++i4) {
        sred[i4 * 128 + rt * 32 + lane] =
            make_float4(a[i4 * 4 + 0], a[i4 * 4 + 1], a[i4 * 4 + 2], a[i4 * 4 + 3]);
    }
}

__device__ __forceinline__ void red_add(float acc[4][8], const float4* sred,
                                        int rt, int lane) {
    float* a = &acc[0][0];
#pragma unroll
    for (int i4 = 0; i4 < 8; ++i4) {
        float4 v = sred[i4 * 128 + rt * 32 + lane];
        a[i4 * 4 + 0] += v.x; a[i4 * 4 + 1] += v.y;
        a[i4 * 4 + 2] += v.z; a[i4 * 4 + 3] += v.w;
    }
}

// rows4: global row indices; h stored pre-rounded to tf32.
__device__ __forceinline__ void cell_update(float acc[4][8],
                                            const float* __restrict__ bias8,
                                            float* __restrict__ creg,
                                            float* __restrict__ hout,
                                            const int* rows4, int cA) {
#pragma unroll
    for (int h = 0; h < 4; ++h) {
        int r = rows4[h];
        float2 hv;
#pragma unroll
        for (int q = 0; q < 2; ++q) {
            int p = h * 2 + q;
            float gi = acc[0][p] + bias8[0 + q];
            float gf = acc[1][p] + bias8[2 + q];
            float gg = acc[2][p] + bias8[4 + q];
            float go = acc[3][p] + bias8[6 + q];
            float cn = sigf(gf) * creg[p] + sigf(gi) * tanh_(gg);
            creg[p] = cn;
            float hv1 = sigf(go) * tanh_(cn);
            if (q == 0) hv.x = __uint_as_float(f2tf(hv1));
            else        hv.y = __uint_as_float(f2tf(hv1));
        }
        __stcg((float2*)&hout[r * HH + cA], hv);
    }
}

__global__ void __launch_bounds__(NTHREADS, 1)
lstm_kernel(const float* __restrict__ x, const float* __restrict__ y,
            const float* __restrict__ Wih0, const float* __restrict__ Whh0,
            const float* __restrict__ bih0, const float* __restrict__ bhh0,
            const float* __restrict__ Wih1, const float* __restrict__ Whh1,
            const float* __restrict__ bih1, const float* __restrict__ bhh1,
            const float* __restrict__ Wlin, const float* __restrict__ blin,
            float* __restrict__ dout, int out_size) {
    extern __shared__ uint4 smw[];
    uint4* sW0base = smw;
    uint4* sW1base = smw + SMEM_W0;
    float4* sred = (float4*)(smw + SMEM_W0 + SMEM_W1);

    const int tid = threadIdx.x;
    const int gtid = blockIdx.x * NTHREADS + tid;
    const int GSTRIDE = NCTA * NTHREADS;

    const int lane = tid & 31;
    const int w = tid >> 5;            // 0..7
    const int rt = w & 3;              // row tile 0..3
    const int kh = w >> 2;             // k-half 0..1
    const int grp = lane >> 2;
    const int tig = lane & 3;
    const int mtile = blockIdx.x >> 6; // 0..1
    const int ub = blockIdx.x & 63;    // 0..63
    const int m0 = mtile * 128;
    const int u0 = ub * 8;
    const int rA = m0 + rt * 32 + grp; // rows rA, +8, +16, +24
    const int cA = u0 + 2 * tig;
    const int rows4[4] = {rA, rA + 8, rA + 16, rA + 24};

    // ------------- prologue: pack this CTA's weight slice into SMEM ---------
    for (int s = tid; s < SMEM_W0; s += NTHREADS) {
        int ln = s & 31;
        int kk = (s >> 5) % NK16_0;
        int g = s / (32 * NK16_0);
        int n = g * HH + u0 + (ln >> 2);
        int k = kk * 16 + (ln & 3) * 4;
        float v[4];
#pragma unroll
        for (int j = 0; j < 4; ++j) {
            int kj = k + j;
            v[j] = (kj < II) ? __ldg(&Wih0[n * II + kj]) : __ldg(&Whh0[n * HH + (kj - II)]);
        }
        sW0base[s] = make_uint4(f2tf(v[0]), f2tf(v[1]), f2tf(v[2]), f2tf(v[3]));
    }
    for (int s = tid; s < SMEM_W1; s += NTHREADS) {
        int ln = s & 31;
        int kk = (s >> 5) % NK16_1;
        int g = s / (32 * NK16_1);
        int n = g * HH + u0 + (ln >> 2);
        int k = kk * 16 + (ln & 3) * 4;
        float v[4];
#pragma unroll
        for (int j = 0; j < 4; ++j) {
            int kj = k + j;
            v[j] = (kj < HH) ? __ldg(&Wih1[n * HH + kj]) : __ldg(&Whh1[n * HH + (kj - HH)]);
        }
        sW1base[s] = make_uint4(f2tf(v[0]), f2tf(v[1]), f2tf(v[2]), f2tf(v[3]));
    }
    // zero initial h1 (h0 buffers are fully written before being read)
    for (int i = gtid; i < BATCH * HH; i += GSTRIDE) {
        g_h1[0][i] = 0.0f;
    }

    float bias8_0[8], bias8_1[8];
#pragma unroll
    for (int g = 0; g < 4; ++g)
#pragma unroll
        for (int q = 0; q < 2; ++q) {
            int n = g * HH + cA + q;
            bias8_0[g * 2 + q] = __ldg(&bih0[n]) + __ldg(&bhh0[n]);
            bias8_1[g * 2 + q] = __ldg(&bih1[n]) + __ldg(&bhh1[n]);
        }

    const uint4* sW0 = sW0base + lane;
    const uint4* sW1 = sW1base + lane;

    float* h0_cur = g_h0[1];
    float* h0_nxt = g_h0[0];
    float* h1_prv = g_h1[0];
    float* h1_cur = g_h1[1];

    float c0reg[8] = {0.f, 0.f, 0.f, 0.f, 0.f, 0.f, 0.f, 0.f};
    float c1reg[8] = {0.f, 0.f, 0.f, 0.f, 0.f, 0.f, 0.f, 0.f};

    const int xoff = tig * 4;
    const float* xA = x + (size_t)rows4[0] * (TT * II) + xoff;
    const float* xB = x + (size_t)rows4[1] * (TT * II) + xoff;
    const float* xC = x + (size_t)rows4[2] * (TT * II) + xoff;
    const float* xD = x + (size_t)rows4[3] * (TT * II) + xoff;
    const int oA = rows4[0] * HH + xoff;
    const int oB = rows4[1] * HH + xoff;
    const int oC = rows4[2] * HH + xoff;
    const int oD = rows4[3] * HH + xoff;

    // per-khalf offsets
    const int hcolOff = kh * 256;      // 16 blocks * 16 floats
    const int wb_f1 = kh * 16;         // W1 blocks for fused span
    const int wb_f0 = 4 + kh * 16;     // W0 blocks for fused span
    const int wb_h1 = 32 + kh * 16;    // W1 blocks for h1 span
    const int wb_x = kh * 2;           // W0 blocks for x span
    const int xcolOff = kh * 32;       // 2 blocks * 16 floats

    unsigned barn = 0;
    gsync(barn);   // prologue visibility

    // ---- layer0(0): h0(0) = cell(x(0)); h-part is zero (h0 init = 0) --------
    {
        float acc0[4][8];
#pragma unroll
        for (int a = 0; a < 4; ++a)
#pragma unroll
            for (int b = 0; b < 8; ++b) acc0[a][b] = 0.0f;
        span<NK16_0, true, 2>(acc0, sW0, wb_x,
                              xA + xcolOff, xB + xcolOff, xC + xcolOff, xD + xcolOff);
        if (kh == 1) red_store(acc0, sred, rt, lane);
        __syncthreads();
        if (kh == 0) {
            red_add(acc0, sred, rt, lane);
            cell_update(acc0, bias8_0, c0reg, h0_cur, rows4, cA);
        }
    }
    gsync(barn);

    // ---- main loop: iteration t computes layer1(t) and layer0(t+1) ----------
    for (int t = 0; t < TT; ++t) {
        float acc1[4][8], acc0[4][8];
#pragma unroll
        for (int a = 0; a < 4; ++a)
#pragma unroll
            for (int b = 0; b < 8; ++b) { acc1[a][b] = 0.0f; acc0[a][b] = 0.0f; }

        // shared h0(t) stream -> layer1 K-half and layer0 h-part K-half
        fused_span(acc1, acc0, sW1, sW0, wb_f1, wb_f0,
                   h0_cur + oA + hcolOff, h0_cur + oB + hcolOff,
                   h0_cur + oC + hcolOff, h0_cur + oD + hcolOff);
        // layer1 h1(t-1) K-half
        span<NK16_1, false, 16>(acc1, sW1, wb_h1,
                                h1_prv + oA + hcolOff, h1_prv + oB + hcolOff,
                                h1_prv + oC + hcolOff, h1_prv + oD + hcolOff);

        // reduce acc1, update layer1 cells
        if (kh == 1) red_store(acc1, sred, rt, lane);
        __syncthreads();
        if (kh == 0) {
            red_add(acc1, sred, rt, lane);
            cell_update(acc1, bias8_1, c1reg, h1_cur, rows4, cA);
        }

        // layer0 x-part: x(t+1) (t=TT-1 recomputes x(TT-1); result unused)
        const int xt = (t < TT - 1) ? (t + 1) : (TT - 1);
        span<NK16_0, true, 2>(acc0, sW0, wb_x,
                              xA + xt * II + xcolOff, xB + xt * II + xcolOff,
                              xC + xt * II + xcolOff, xD + xt * II + xcolOff);

        __syncthreads();   // sred safe to overwrite
        if (kh == 1) red_store(acc0, sred, rt, lane);
        __syncthreads();
        if (kh == 0) {
            red_add(acc0, sred, rt, lane);
            cell_update(acc0, bias8_0, c0reg, h0_nxt, rows4, cA);
        }

        if (t < TT - 1) gsync(barn);

        float* tmp = h0_cur; h0_cur = h0_nxt; h0_nxt = tmp;
        tmp = h1_prv; h1_prv = h1_cur; h1_cur = tmp;
    }

    // ---------------- final barrier: non-zero CTAs arrive and exit ----------
    __threadfence();
    __syncthreads();
    if (tid == 0) atomicAdd(&g_bar, 1u);
    barn += NCTA;
    if (blockIdx.x != 0) return;

    if (tid == 0) {
        while (*(volatile unsigned*)&g_bar < barn) {}
        __threadfence();
        *(volatile unsigned*)&g_bar = 0u;  // reset for next graph replay
    }
    __syncthreads();

    // ---------------- epilogue on CTA 0: linear head + MSE loss --------------
    const float* h1fin = h1_prv;           // final h1 after last swap
    int b = tid;                           // 0..255 = batch row
    const float* hrow = h1fin + (size_t)b * HH;
    float s = __ldg(&blin[0]);
#pragma unroll 8
    for (int c2 = 0; c2 < HH; c2 += 4) {
        float4 wv = __ldg((const float4*)(Wlin + c2));
        float4 h4 = __ldcg((const float4*)(hrow + c2));
        s += h4.x * wv.x + h4.y * wv.y + h4.z * wv.z + h4.w * wv.w;
    }

    __shared__ float red[NTHREADS];
    float d = s - __ldg(&y[b]);
    red[b] = d * d;
    __syncthreads();
#pragma unroll
    for (int off = 128; off > 0; off >>= 1) {
        if (b < off) red[b] += red[b + off];
        __syncthreads();
    }
    float loss = red[0] * (1.0f / BATCH);

    if (out_size >= BATCH + 1) {
        dout[b] = s;
        if (b == 0) dout[BATCH] = loss;
        for (int i2 = BATCH + 1 + b; i2 < out_size; i2 += NTHREADS) dout[i2] = 0.0f;
    } else if (out_size == BATCH) {
        dout[b] = s;
    } else if (out_size == 1) {
        if (b == 0) dout[0] = loss;
    } else {
        if (b < out_size) dout[b] = (b < BATCH) ? s : loss;
    }
}

extern "C" void kernel_launch(void* const* d_in, const int* in_sizes, int n_in,
                              void* d_out, int out_size) {
    const float* x    = (const float*)d_in[0];
    const float* y    = (const float*)d_in[1];
    const float* Wih0 = (const float*)d_in[2];
    const float* Whh0 = (const float*)d_in[3];
    const float* bih0 = (const float*)d_in[4];
    const float* bhh0 = (const float*)d_in[5];
    const float* Wih1 = (const float*)d_in[6];
    const float* Whh1 = (const float*)d_in[7];
    const float* bih1 = (const float*)d_in[8];
    const float* bhh1 = (const float*)d_in[9];
    const float* Wlin = (const float*)d_in[10];
    const float* blin = (const float*)d_in[11];

    cudaFuncSetAttribute(lstm_kernel, cudaFuncAttributeMaxDynamicSharedMemorySize,
                         SMEM_BYTES);
    lstm_kernel<<<NCTA, NTHREADS, SMEM_BYTES>>>(x, y, Wih0, Whh0, bih0, bhh0,
                                                Wih1, Whh1, bih1, bhh1, Wlin, blin,
                                                (float*)d_out, out_size);
}

// round 6
// speedup vs baseline: 1.3062x; 1.0167x over previous
#include <cuda_runtime.h>
#include <cstdint>

// ---------------------------------------------------------------------------
// HSLSTMRegressor: 2-layer LSTM (B=256, T=512, I=64, H=512) + linear head + MSE
// R5 (resubmit; round-5 bench was an infra failure, no kernel signal):
//     R4 structure (128 CTAs x 256 thr, 4 row-tiles x 2 k-halves split-K,
//     fused h0 span, 1 grid barrier/step, weights in SMEM) with issue-side
//     fixes: fully-unrolled spans (compile-time modulo prefetch buffers, no
//     rotation MOVs), depth-4 act prefetch, hoisted weight base pointers,
//     x(t+1) span overlapped with the acc1 reduction.
// ---------------------------------------------------------------------------

#define BATCH 256
#define TT    512
#define II    64
#define HH    512
#define NCTA  128
#define NTHREADS 256
#define NK16_0 36   // (64 + 512) / 16
#define NK16_1 64   // (512 + 512) / 16
#define SMEM_W0 (4 * NK16_0 * 32)          // uint4 elements, layer0 slice
#define SMEM_W1 (4 * NK16_1 * 32)          // uint4 elements, layer1 slice
#define SMEM_WBYTES ((SMEM_W0 + SMEM_W1) * 16)
#define SMEM_RED_FLOATS (4 * 32 * 32)      // [chunk i4][rt][lane] float4-chunked
#define SMEM_BYTES (SMEM_WBYTES + SMEM_RED_FLOATS * 4)

__device__ float g_h0[2][BATCH * HH];
__device__ float g_h1[2][BATCH * HH];
__device__ unsigned g_bar = 0;   // grid barrier counter (reset at kernel end)

__device__ __forceinline__ unsigned f2tf(float f) {
    unsigned u;
    asm("cvt.rna.tf32.f32 %0, %1;" : "=r"(u) : "f"(f));
    return u;
}

__device__ __forceinline__ void mma_tf32(float* c,
                                         unsigned a0, unsigned a1, unsigned a2, unsigned a3,
                                         unsigned b0, unsigned b1) {
    asm volatile(
        "mma.sync.aligned.m16n8k8.row.col.f32.tf32.tf32.f32 "
        "{%0,%1,%2,%3},{%4,%5,%6,%7},{%8,%9},{%0,%1,%2,%3};"
        : "+f"(c[0]), "+f"(c[1]), "+f"(c[2]), "+f"(c[3])
        : "r"(a0), "r"(a1), "r"(a2), "r"(a3), "r"(b0), "r"(b1));
}

__device__ __forceinline__ float sigf(float x) {
    return __fdividef(1.0f, 1.0f + __expf(-x));
}
__device__ __forceinline__ float tanh_(float x) {
    float e = __expf(-2.0f * fabsf(x));
    float r = __fdividef(1.0f - e, 1.0f + e);
    return copysignf(r, x);
}

__device__ __forceinline__ void gsync(unsigned& barn) {
    __threadfence();
    __syncthreads();
    if (threadIdx.x == 0) {
        atomicAdd(&g_bar, 1u);
        unsigned tgt = barn + (unsigned)gridDim.x;
        while (*(volatile unsigned*)&g_bar < tgt) {}
        __threadfence();
    }
    barn += (unsigned)gridDim.x;
    __syncthreads();
}

struct Frag {
    unsigned a[4], b[4], c[4], d[4];
};

template <bool CVT>
__device__ __forceinline__ Frag cvt_frag(float4 va, float4 vb, float4 vc, float4 vd) {
    Frag f;
    if (CVT) {
        f.a[0] = f2tf(va.x); f.a[1] = f2tf(va.y); f.a[2] = f2tf(va.z); f.a[3] = f2tf(va.w);
        f.b[0] = f2tf(vb.x); f.b[1] = f2tf(vb.y); f.b[2] = f2tf(vb.z); f.b[3] = f2tf(vb.w);
        f.c[0] = f2tf(vc.x); f.c[1] = f2tf(vc.y); f.c[2] = f2tf(vc.z); f.c[3] = f2tf(vc.w);
        f.d[0] = f2tf(vd.x); f.d[1] = f2tf(vd.y); f.d[2] = f2tf(vd.z); f.d[3] = f2tf(vd.w);
    } else {
        f.a[0] = __float_as_uint(va.x); f.a[1] = __float_as_uint(va.y);
        f.a[2] = __float_as_uint(va.z); f.a[3] = __float_as_uint(va.w);
        f.b[0] = __float_as_uint(vb.x); f.b[1] = __float_as_uint(vb.y);
        f.b[2] = __float_as_uint(vb.z); f.b[3] = __float_as_uint(vb.w);
        f.c[0] = __float_as_uint(vc.x); f.c[1] = __float_as_uint(vc.y);
        f.c[2] = __float_as_uint(vc.z); f.c[3] = __float_as_uint(vc.w);
        f.d[0] = __float_as_uint(vd.x); f.d[1] = __float_as_uint(vd.y);
        f.d[2] = __float_as_uint(vd.z); f.d[3] = __float_as_uint(vd.w);
    }
    return f;
}

__device__ __forceinline__ void mma_gate(float* acc8, const Frag& f, uint4 q) {
    mma_tf32(acc8 + 0, f.a[0], f.b[0], f.a[1], f.b[1], q.x, q.y);
    mma_tf32(acc8 + 0, f.a[2], f.b[2], f.a[3], f.b[3], q.z, q.w);
    mma_tf32(acc8 + 4, f.c[0], f.d[0], f.c[1], f.d[1], q.x, q.y);
    mma_tf32(acc8 + 4, f.c[2], f.d[2], f.c[3], f.d[3], q.z, q.w);
}

// Fully-unrolled span over NBLK compile-time k16 blocks.
// w0..w3: per-gate weight base pointers (SMEM, already +lane and +k-offset).
// Acts advance 16 floats per block. Modulo-DEPTH prefetch buffers; prefetch
// issued after the consuming MMAs (no WAR copies), compile-time bounded.
template <bool CVT, int NBLK>
__device__ __forceinline__ void span_n(float acc[4][8],
                                       const uint4* __restrict__ w0, const uint4* __restrict__ w1,
                                       const uint4* __restrict__ w2, const uint4* __restrict__ w3,
                                       const float* __restrict__ pA, const float* __restrict__ pB,
                                       const float* __restrict__ pC, const float* __restrict__ pD) {
    constexpr int DEPTH = (NBLK >= 4) ? 4 : NBLK;
    float4 bA[DEPTH], bB[DEPTH], bC[DEPTH], bD[DEPTH];
#pragma unroll
    for (int d = 0; d < DEPTH; ++d) {
        bA[d] = __ldcg((const float4*)(pA + d * 16));
        bB[d] = __ldcg((const float4*)(pB + d * 16));
        bC[d] = __ldcg((const float4*)(pC + d * 16));
        bD[d] = __ldcg((const float4*)(pD + d * 16));
    }
#pragma unroll
    for (int j = 0; j < NBLK; ++j) {
        const int s = j % DEPTH;
        uint4 q0 = w0[j * 32];
        uint4 q1 = w1[j * 32];
        uint4 q2 = w2[j * 32];
        uint4 q3 = w3[j * 32];
        Frag f = cvt_frag<CVT>(bA[s], bB[s], bC[s], bD[s]);
        mma_gate(acc[0], f, q0);
        mma_gate(acc[1], f, q1);
        mma_gate(acc[2], f, q2);
        mma_gate(acc[3], f, q3);
        if (j + DEPTH < NBLK) {
            bA[s] = __ldcg((const float4*)(pA + (j + DEPTH) * 16));
            bB[s] = __ldcg((const float4*)(pB + (j + DEPTH) * 16));
            bC[s] = __ldcg((const float4*)(pC + (j + DEPTH) * 16));
            bD[s] = __ldcg((const float4*)(pD + (j + DEPTH) * 16));
        }
    }
}

// Fused span over NBLK shared-h0 blocks: one act stream feeds acc1 (W1) and
// acc0 (W0). Same unroll/prefetch scheme.
template <int NBLK>
__device__ __forceinline__ void fused_span_n(float acc1[4][8], float acc0[4][8],
                                             const uint4* __restrict__ p0, const uint4* __restrict__ p1,
                                             const uint4* __restrict__ p2, const uint4* __restrict__ p3,
                                             const uint4* __restrict__ q0p, const uint4* __restrict__ q1p,
                                             const uint4* __restrict__ q2p, const uint4* __restrict__ q3p,
                                             const float* __restrict__ pA, const float* __restrict__ pB,
                                             const float* __restrict__ pC, const float* __restrict__ pD) {
    constexpr int DEPTH = (NBLK >= 4) ? 4 : NBLK;
    float4 bA[DEPTH], bB[DEPTH], bC[DEPTH], bD[DEPTH];
#pragma unroll
    for (int d = 0; d < DEPTH; ++d) {
        bA[d] = __ldcg((const float4*)(pA + d * 16));
        bB[d] = __ldcg((const float4*)(pB + d * 16));
        bC[d] = __ldcg((const float4*)(pC + d * 16));
        bD[d] = __ldcg((const float4*)(pD + d * 16));
    }
#pragma unroll
    for (int j = 0; j < NBLK; ++j) {
        const int s = j % DEPTH;
        uint4 p0v = p0[j * 32];
        uint4 p1v = p1[j * 32];
        uint4 p2v = p2[j * 32];
        uint4 p3v = p3[j * 32];
        uint4 q0v = q0p[j * 32];
        uint4 q1v = q1p[j * 32];
        uint4 q2v = q2p[j * 32];
        uint4 q3v = q3p[j * 32];
        Frag f = cvt_frag<false>(bA[s], bB[s], bC[s], bD[s]);
        mma_gate(acc1[0], f, p0v);
        mma_gate(acc1[1], f, p1v);
        mma_gate(acc1[2], f, p2v);
        mma_gate(acc1[3], f, p3v);
        mma_gate(acc0[0], f, q0v);
        mma_gate(acc0[1], f, q1v);
        mma_gate(acc0[2], f, q2v);
        mma_gate(acc0[3], f, q3v);
        if (j + DEPTH < NBLK) {
            bA[s] = __ldcg((const float4*)(pA + (j + DEPTH) * 16));
            bB[s] = __ldcg((const float4*)(pB + (j + DEPTH) * 16));
            bC[s] = __ldcg((const float4*)(pC + (j + DEPTH) * 16));
            bD[s] = __ldcg((const float4*)(pD + (j + DEPTH) * 16));
        }
    }
}

// ---- split-K reduction through smem: layout [i4][rt][lane] of float4 --------
__device__ __forceinline__ void red_store(const float acc[4][8], float4* sred,
                                          int rt, int lane) {
    const float* a = &acc[0][0];
#pragma unroll
    for (int i4 = 0; i4 < 8; ++i4) {
        sred[i4 * 128 + rt * 32 + lane] =
            make_float4(a[i4 * 4 + 0], a[i4 * 4 + 1], a[i4 * 4 + 2], a[i4 * 4 + 3]);
    }
}

__device__ __forceinline__ void red_add(float acc[4][8], const float4* sred,
                                        int rt, int lane) {
    float* a = &acc[0][0];
#pragma unroll
    for (int i4 = 0; i4 < 8; ++i4) {
        float4 v = sred[i4 * 128 + rt * 32 + lane];
        a[i4 * 4 + 0] += v.x; a[i4 * 4 + 1] += v.y;
        a[i4 * 4 + 2] += v.z; a[i4 * 4 + 3] += v.w;
    }
}

// rows4: global row indices; h stored pre-rounded to tf32.
__device__ __forceinline__ void cell_update(float acc[4][8],
                                            const float* __restrict__ bias8,
                                            float* __restrict__ creg,
                                            float* __restrict__ hout,
                                            const int* rows4, int cA) {
#pragma unroll
    for (int h = 0; h < 4; ++h) {
        int r = rows4[h];
        float2 hv;
#pragma unroll
        for (int q = 0; q < 2; ++q) {
            int p = h * 2 + q;
            float gi = acc[0][p] + bias8[0 + q];
            float gf = acc[1][p] + bias8[2 + q];
            float gg = acc[2][p] + bias8[4 + q];
            float go = acc[3][p] + bias8[6 + q];
            float cn = sigf(gf) * creg[p] + sigf(gi) * tanh_(gg);
            creg[p] = cn;
            float hv1 = sigf(go) * tanh_(cn);
            if (q == 0) hv.x = __uint_as_float(f2tf(hv1));
            else        hv.y = __uint_as_float(f2tf(hv1));
        }
        __stcg((float2*)&hout[r * HH + cA], hv);
    }
}

__global__ void __launch_bounds__(NTHREADS, 1)
lstm_kernel(const float* __restrict__ x, const float* __restrict__ y,
            const float* __restrict__ Wih0, const float* __restrict__ Whh0,
            const float* __restrict__ bih0, const float* __restrict__ bhh0,
            const float* __restrict__ Wih1, const float* __restrict__ Whh1,
            const float* __restrict__ bih1, const float* __restrict__ bhh1,
            const float* __restrict__ Wlin, const float* __restrict__ blin,
            float* __restrict__ dout, int out_size) {
    extern __shared__ uint4 smw[];
    uint4* sW0base = smw;
    uint4* sW1base = smw + SMEM_W0;
    float4* sred = (float4*)(smw + SMEM_W0 + SMEM_W1);

    const int tid = threadIdx.x;
    const int gtid = blockIdx.x * NTHREADS + tid;
    const int GSTRIDE = NCTA * NTHREADS;

    const int lane = tid & 31;
    const int w = tid >> 5;            // 0..7
    const int rt = w & 3;              // row tile 0..3
    const int kh = w >> 2;             // k-half 0..1
    const int grp = lane >> 2;
    const int tig = lane & 3;
    const int mtile = blockIdx.x >> 6; // 0..1
    const int ub = blockIdx.x & 63;    // 0..63
    const int m0 = mtile * 128;
    const int u0 = ub * 8;
    const int rA = m0 + rt * 32 + grp; // rows rA, +8, +16, +24
    const int cA = u0 + 2 * tig;
    const int rows4[4] = {rA, rA + 8, rA + 16, rA + 24};

    // ------------- prologue: pack this CTA's weight slice into SMEM ---------
    for (int s = tid; s < SMEM_W0; s += NTHREADS) {
        int ln = s & 31;
        int kk = (s >> 5) % NK16_0;
        int g = s / (32 * NK16_0);
        int n = g * HH + u0 + (ln >> 2);
        int k = kk * 16 + (ln & 3) * 4;
        float v[4];
#pragma unroll
        for (int j = 0; j < 4; ++j) {
            int kj = k + j;
            v[j] = (kj < II) ? __ldg(&Wih0[n * II + kj]) : __ldg(&Whh0[n * HH + (kj - II)]);
        }
        sW0base[s] = make_uint4(f2tf(v[0]), f2tf(v[1]), f2tf(v[2]), f2tf(v[3]));
    }
    for (int s = tid; s < SMEM_W1; s += NTHREADS) {
        int ln = s & 31;
        int kk = (s >> 5) % NK16_1;
        int g = s / (32 * NK16_1);
        int n = g * HH + u0 + (ln >> 2);
        int k = kk * 16 + (ln & 3) * 4;
        float v[4];
#pragma unroll
        for (int j = 0; j < 4; ++j) {
            int kj = k + j;
            v[j] = (kj < HH) ? __ldg(&Wih1[n * HH + kj]) : __ldg(&Whh1[n * HH + (kj - HH)]);
        }
        sW1base[s] = make_uint4(f2tf(v[0]), f2tf(v[1]), f2tf(v[2]), f2tf(v[3]));
    }
    // zero initial h1 (h0 buffers are fully written before being read)
    for (int i = gtid; i < BATCH * HH; i += GSTRIDE) {
        g_h1[0][i] = 0.0f;
    }

    float bias8_0[8], bias8_1[8];
#pragma unroll
    for (int g = 0; g < 4; ++g)
#pragma unroll
        for (int q = 0; q < 2; ++q) {
            int n = g * HH + cA + q;
            bias8_0[g * 2 + q] = __ldg(&bih0[n]) + __ldg(&bhh0[n]);
            bias8_1[g * 2 + q] = __ldg(&bih1[n]) + __ldg(&bhh1[n]);
        }

    // per-khalf block offsets
    const int hcolOff = kh * 256;      // 16 blocks * 16 floats
    const int wb_f1 = kh * 16;         // W1 blocks for fused span
    const int wb_f0 = 4 + kh * 16;     // W0 blocks for fused span
    const int wb_h1 = 32 + kh * 16;    // W1 blocks for h1 span
    const int wb_x = kh * 2;           // W0 blocks for x span
    const int xcolOff = kh * 32;       // 2 blocks * 16 floats

    // hoisted per-gate weight base pointers (loop-invariant)
    const uint4* sW0 = sW0base + lane;
    const uint4* sW1 = sW1base + lane;
    const uint4* wf1_0 = sW1 + (0 * NK16_1 + wb_f1) * 32;
    const uint4* wf1_1 = sW1 + (1 * NK16_1 + wb_f1) * 32;
    const uint4* wf1_2 = sW1 + (2 * NK16_1 + wb_f1) * 32;
    const uint4* wf1_3 = sW1 + (3 * NK16_1 + wb_f1) * 32;
    const uint4* wf0_0 = sW0 + (0 * NK16_0 + wb_f0) * 32;
    const uint4* wf0_1 = sW0 + (1 * NK16_0 + wb_f0) * 32;
    const uint4* wf0_2 = sW0 + (2 * NK16_0 + wb_f0) * 32;
    const uint4* wf0_3 = sW0 + (3 * NK16_0 + wb_f0) * 32;
    const uint4* wh1_0 = sW1 + (0 * NK16_1 + wb_h1) * 32;
    const uint4* wh1_1 = sW1 + (1 * NK16_1 + wb_h1) * 32;
    const uint4* wh1_2 = sW1 + (2 * NK16_1 + wb_h1) * 32;
    const uint4* wh1_3 = sW1 + (3 * NK16_1 + wb_h1) * 32;
    const uint4* wx0_0 = sW0 + (0 * NK16_0 + wb_x) * 32;
    const uint4* wx0_1 = sW0 + (1 * NK16_0 + wb_x) * 32;
    const uint4* wx0_2 = sW0 + (2 * NK16_0 + wb_x) * 32;
    const uint4* wx0_3 = sW0 + (3 * NK16_0 + wb_x) * 32;

    float* h0_cur = g_h0[1];
    float* h0_nxt = g_h0[0];
    float* h1_prv = g_h1[0];
    float* h1_cur = g_h1[1];

    float c0reg[8] = {0.f, 0.f, 0.f, 0.f, 0.f, 0.f, 0.f, 0.f};
    float c1reg[8] = {0.f, 0.f, 0.f, 0.f, 0.f, 0.f, 0.f, 0.f};

    const int xoff = tig * 4;
    const float* xA = x + (size_t)rows4[0] * (TT * II) + xoff + xcolOff;
    const float* xB = x + (size_t)rows4[1] * (TT * II) + xoff + xcolOff;
    const float* xC = x + (size_t)rows4[2] * (TT * II) + xoff + xcolOff;
    const float* xD = x + (size_t)rows4[3] * (TT * II) + xoff + xcolOff;
    const int oA = rows4[0] * HH + xoff + hcolOff;
    const int oB = rows4[1] * HH + xoff + hcolOff;
    const int oC = rows4[2] * HH + xoff + hcolOff;
    const int oD = rows4[3] * HH + xoff + hcolOff;

    unsigned barn = 0;
    gsync(barn);   // prologue visibility

    // ---- layer0(0): h0(0) = cell(x(0)); h-part is zero (h0 init = 0) --------
    {
        float acc0[4][8];
#pragma unroll
        for (int a = 0; a < 4; ++a)
#pragma unroll
            for (int b = 0; b < 8; ++b) acc0[a][b] = 0.0f;
        span_n<true, 2>(acc0, wx0_0, wx0_1, wx0_2, wx0_3, xA, xB, xC, xD);
        if (kh == 1) red_store(acc0, sred, rt, lane);
        __syncthreads();
        if (kh == 0) {
            red_add(acc0, sred, rt, lane);
            cell_update(acc0, bias8_0, c0reg, h0_cur, rows4, cA);
        }
    }
    gsync(barn);

    // ---- main loop: iteration t computes layer1(t) and layer0(t+1) ----------
    for (int t = 0; t < TT; ++t) {
        float acc1[4][8], acc0[4][8];
#pragma unroll
        for (int a = 0; a < 4; ++a)
#pragma unroll
            for (int b = 0; b < 8; ++b) { acc1[a][b] = 0.0f; acc0[a][b] = 0.0f; }

        // shared h0(t) stream -> layer1 K-half and layer0 h-part K-half
        fused_span_n<16>(acc1, acc0,
                         wf1_0, wf1_1, wf1_2, wf1_3,
                         wf0_0, wf0_1, wf0_2, wf0_3,
                         h0_cur + oA, h0_cur + oB, h0_cur + oC, h0_cur + oD);
        // layer1 h1(t-1) K-half
        span_n<false, 16>(acc1, wh1_0, wh1_1, wh1_2, wh1_3,
                          h1_prv + oA, h1_prv + oB, h1_prv + oC, h1_prv + oD);
        // layer0 x-part: x(t+1) (t=TT-1 recomputes x(TT-1); result unused) —
        // issued before the acc1 reduction so its L2 loads overlap the syncs.
        const int xt = (t < TT - 1) ? (t + 1) : (TT - 1);
        span_n<true, 2>(acc0, wx0_0, wx0_1, wx0_2, wx0_3,
                        xA + xt * II, xB + xt * II, xC + xt * II, xD + xt * II);

        // reduce acc1, update layer1 cells
        if (kh == 1) red_store(acc1, sred, rt, lane);
        __syncthreads();
        if (kh == 0) {
            red_add(acc1, sred, rt, lane);
            cell_update(acc1, bias8_1, c1reg, h1_cur, rows4, cA);
        }
        __syncthreads();   // sred safe to overwrite
        if (kh == 1) red_store(acc0, sred, rt, lane);
        __syncthreads();
        if (kh == 0) {
            red_add(acc0, sred, rt, lane);
            cell_update(acc0, bias8_0, c0reg, h0_nxt, rows4, cA);
        }

        if (t < TT - 1) gsync(barn);

        float* tmp = h0_cur; h0_cur = h0_nxt; h0_nxt = tmp;
        tmp = h1_prv; h1_prv = h1_cur; h1_cur = tmp;
    }

    // ---------------- final barrier: non-zero CTAs arrive and exit ----------
    __threadfence();
    __syncthreads();
    if (tid == 0) atomicAdd(&g_bar, 1u);
    barn += NCTA;
    if (blockIdx.x != 0) return;

    if (tid == 0) {
        while (*(volatile unsigned*)&g_bar < barn) {}
        __threadfence();
        *(volatile unsigned*)&g_bar = 0u;  // reset for next graph replay
    }
    __syncthreads();

    // ---------------- epilogue on CTA 0: linear head + MSE loss --------------
    const float* h1fin = h1_prv;           // final h1 after last swap
    int b = tid;                           // 0..255 = batch row
    const float* hrow = h1fin + (size_t)b * HH;
    float s = __ldg(&blin[0]);
#pragma unroll 8
    for (int c2 = 0; c2 < HH; c2 += 4) {
        float4 wv = __ldg((const float4*)(Wlin + c2));
        float4 h4 = __ldcg((const float4*)(hrow + c2));
        s += h4.x * wv.x + h4.y * wv.y + h4.z * wv.z + h4.w * wv.w;
    }

    __shared__ float red[NTHREADS];
    float d = s - __ldg(&y[b]);
    red[b] = d * d;
    __syncthreads();
#pragma unroll
    for (int off = 128; off > 0; off >>= 1) {
        if (b < off) red[b] += red[b + off];
        __syncthreads();
    }
    float loss = red[0] * (1.0f / BATCH);

    if (out_size >= BATCH + 1) {
        dout[b] = s;
        if (b == 0) dout[BATCH] = loss;
        for (int i2 = BATCH + 1 + b; i2 < out_size; i2 += NTHREADS) dout[i2] = 0.0f;
    } else if (out_size == BATCH) {
        dout[b] = s;
    } else if (out_size == 1) {
        if (b == 0) dout[0] = loss;
    } else {
        if (b < out_size) dout[b] = (b < BATCH) ? s : loss;
    }
}

extern "C" void kernel_launch(void* const* d_in, const int* in_sizes, int n_in,
                              void* d_out, int out_size) {
    const float* x    = (const float*)d_in[0];
    const float* y    = (const float*)d_in[1];
    const float* Wih0 = (const float*)d_in[2];
    const float* Whh0 = (const float*)d_in[3];
    const float* bih0 = (const float*)d_in[4];
    const float* bhh0 = (const float*)d_in[5];
    const float* Wih1 = (const float*)d_in[6];
    const float* Whh1 = (const float*)d_in[7];
    const float* bih1 = (const float*)d_in[8];
    const float* bhh1 = (const float*)d_in[9];
    const float* Wlin = (const float*)d_in[10];
    const float* blin = (const float*)d_in[11];

    cudaFuncSetAttribute(lstm_kernel, cudaFuncAttributeMaxDynamicSharedMemorySize,
                         SMEM_BYTES);
    lstm_kernel<<<NCTA, NTHREADS, SMEM_BYTES>>>(x, y, Wih0, Whh0, bih0, bhh0,
                                                Wih1, Whh1, bih1, bhh1, Wlin, blin,
                                                (float*)d_out, out_size);
}

// round 7
// speedup vs baseline: 1.4179x; 1.0855x over previous
#include <cuda_runtime.h>
#include <cstdint>

// ---------------------------------------------------------------------------
// HSLSTMRegressor: 2-layer LSTM (B=256, T=512, I=64, H=512) + linear head + MSE
// R7: latency/serialization attack on the R5 structure:
//   - per-mtile grid barriers (cohort 64, separate cache lines)
//   - x(t+2) span computed INSIDE the barrier wait window (acc0 carries over)
//   - balanced epilogue: kh=0 updates layer1, kh=1 updates layer0 (MUFU halved)
//   - merged fused+h1 span: one L2-latency head per step instead of two
// ---------------------------------------------------------------------------

#define BATCH 256
#define TT    512
#define II    64
#define HH    512
#define NCTA  128
#define NTHREADS 256
#define NK16_0 36   // (64 + 512) / 16
#define NK16_1 64   // (512 + 512) / 16
#define SMEM_W0 (4 * NK16_0 * 32)          // uint4 elements, layer0 slice
#define SMEM_W1 (4 * NK16_1 * 32)          // uint4 elements, layer1 slice
#define SMEM_WBYTES ((SMEM_W0 + SMEM_W1) * 16)
#define SMEM_BYTES (SMEM_WBYTES + 4096 * 4)   // + 16KB reduction buffer

__device__ float g_h0[2][BATCH * HH];
__device__ float g_h1[2][BATCH * HH];
__device__ unsigned g_barM[64];   // [0]=mtile0, [32]=mtile1 (128B apart)
__device__ unsigned g_barF = 0;   // final global barrier

__device__ __forceinline__ unsigned f2tf(float f) {
    unsigned u;
    asm("cvt.rna.tf32.f32 %0, %1;" : "=r"(u) : "f"(f));
    return u;
}

__device__ __forceinline__ void mma_tf32(float* c,
                                         unsigned a0, unsigned a1, unsigned a2, unsigned a3,
                                         unsigned b0, unsigned b1) {
    asm volatile(
        "mma.sync.aligned.m16n8k8.row.col.f32.tf32.tf32.f32 "
        "{%0,%1,%2,%3},{%4,%5,%6,%7},{%8,%9},{%0,%1,%2,%3};"
        : "+f"(c[0]), "+f"(c[1]), "+f"(c[2]), "+f"(c[3])
        : "r"(a0), "r"(a1), "r"(a2), "r"(a3), "r"(b0), "r"(b1));
}

__device__ __forceinline__ float sigf(float x) {
    return __fdividef(1.0f, 1.0f + __expf(-x));
}
__device__ __forceinline__ float tanh_(float x) {
    float e = __expf(-2.0f * fabsf(x));
    float r = __fdividef(1.0f - e, 1.0f + e);
    return copysignf(r, x);
}

struct Frag {
    unsigned a[4], b[4], c[4], d[4];
};

template <bool CVT>
__device__ __forceinline__ Frag cvt_frag(float4 va, float4 vb, float4 vc, float4 vd) {
    Frag f;
    if (CVT) {
        f.a[0] = f2tf(va.x); f.a[1] = f2tf(va.y); f.a[2] = f2tf(va.z); f.a[3] = f2tf(va.w);
        f.b[0] = f2tf(vb.x); f.b[1] = f2tf(vb.y); f.b[2] = f2tf(vb.z); f.b[3] = f2tf(vb.w);
        f.c[0] = f2tf(vc.x); f.c[1] = f2tf(vc.y); f.c[2] = f2tf(vc.z); f.c[3] = f2tf(vc.w);
        f.d[0] = f2tf(vd.x); f.d[1] = f2tf(vd.y); f.d[2] = f2tf(vd.z); f.d[3] = f2tf(vd.w);
    } else {
        f.a[0] = __float_as_uint(va.x); f.a[1] = __float_as_uint(va.y);
        f.a[2] = __float_as_uint(va.z); f.a[3] = __float_as_uint(va.w);
        f.b[0] = __float_as_uint(vb.x); f.b[1] = __float_as_uint(vb.y);
        f.b[2] = __float_as_uint(vb.z); f.b[3] = __float_as_uint(vb.w);
        f.c[0] = __float_as_uint(vc.x); f.c[1] = __float_as_uint(vc.y);
        f.c[2] = __float_as_uint(vc.z); f.c[3] = __float_as_uint(vc.w);
        f.d[0] = __float_as_uint(vd.x); f.d[1] = __float_as_uint(vd.y);
        f.d[2] = __float_as_uint(vd.z); f.d[3] = __float_as_uint(vd.w);
    }
    return f;
}

__device__ __forceinline__ void mma_gate(float* acc8, const Frag& f, uint4 q) {
    mma_tf32(acc8 + 0, f.a[0], f.b[0], f.a[1], f.b[1], q.x, q.y);
    mma_tf32(acc8 + 0, f.a[2], f.b[2], f.a[3], f.b[3], q.z, q.w);
    mma_tf32(acc8 + 4, f.c[0], f.d[0], f.c[1], f.d[1], q.x, q.y);
    mma_tf32(acc8 + 4, f.c[2], f.d[2], f.c[3], f.d[3], q.z, q.w);
}

// Merged span over 16 k16-blocks of BOTH per-step act streams:
//   h0(t) stream -> acc1 (W1 fused half) + acc0 (W0 h-part half)
//   h1(t-1) stream -> acc1 (W1 h1 half)
// Both streams prefetched depth-2 up front: one L2-latency head per step.
__device__ __forceinline__ void merged_span(float acc1[4][8], float acc0[4][8],
                                            const uint4* __restrict__ pW1f,
                                            const uint4* __restrict__ pW0f,
                                            const uint4* __restrict__ pW1h,
                                            const float* __restrict__ fA, const float* __restrict__ fB,
                                            const float* __restrict__ fC, const float* __restrict__ fD,
                                            const float* __restrict__ hA, const float* __restrict__ hB,
                                            const float* __restrict__ hC, const float* __restrict__ hD) {
    float4 bfA[2], bfB[2], bfC[2], bfD[2];
    float4 bhA[2], bhB[2], bhC[2], bhD[2];
#pragma unroll
    for (int d = 0; d < 2; ++d) {
        bfA[d] = __ldcg((const float4*)(fA + d * 16));
        bfB[d] = __ldcg((const float4*)(fB + d * 16));
        bfC[d] = __ldcg((const float4*)(fC + d * 16));
        bfD[d] = __ldcg((const float4*)(fD + d * 16));
        bhA[d] = __ldcg((const float4*)(hA + d * 16));
        bhB[d] = __ldcg((const float4*)(hB + d * 16));
        bhC[d] = __ldcg((const float4*)(hC + d * 16));
        bhD[d] = __ldcg((const float4*)(hD + d * 16));
    }
#pragma unroll
    for (int j = 0; j < 16; ++j) {
        const int s = j & 1;
        uint4 w10 = pW1f[(0 * NK16_1 + j) * 32];
        uint4 w11 = pW1f[(1 * NK16_1 + j) * 32];
        uint4 w12 = pW1f[(2 * NK16_1 + j) * 32];
        uint4 w13 = pW1f[(3 * NK16_1 + j) * 32];
        uint4 w00 = pW0f[(0 * NK16_0 + j) * 32];
        uint4 w01 = pW0f[(1 * NK16_0 + j) * 32];
        uint4 w02 = pW0f[(2 * NK16_0 + j) * 32];
        uint4 w03 = pW0f[(3 * NK16_0 + j) * 32];
        uint4 v10 = pW1h[(0 * NK16_1 + j) * 32];
        uint4 v11 = pW1h[(1 * NK16_1 + j) * 32];
        uint4 v12 = pW1h[(2 * NK16_1 + j) * 32];
        uint4 v13 = pW1h[(3 * NK16_1 + j) * 32];
        Frag ff = cvt_frag<false>(bfA[s], bfB[s], bfC[s], bfD[s]);
        Frag fh = cvt_frag<false>(bhA[s], bhB[s], bhC[s], bhD[s]);
        mma_gate(acc1[0], ff, w10);
        mma_gate(acc1[1], ff, w11);
        mma_gate(acc1[2], ff, w12);
        mma_gate(acc1[3], ff, w13);
        mma_gate(acc0[0], ff, w00);
        mma_gate(acc0[1], ff, w01);
        mma_gate(acc0[2], ff, w02);
        mma_gate(acc0[3], ff, w03);
        mma_gate(acc1[0], fh, v10);
        mma_gate(acc1[1], fh, v11);
        mma_gate(acc1[2], fh, v12);
        mma_gate(acc1[3], fh, v13);
        if (j + 2 < 16) {
            bfA[s] = __ldcg((const float4*)(fA + (j + 2) * 16));
            bfB[s] = __ldcg((const float4*)(fB + (j + 2) * 16));
            bfC[s] = __ldcg((const float4*)(fC + (j + 2) * 16));
            bfD[s] = __ldcg((const float4*)(fD + (j + 2) * 16));
            bhA[s] = __ldcg((const float4*)(hA + (j + 2) * 16));
            bhB[s] = __ldcg((const float4*)(hB + (j + 2) * 16));
            bhC[s] = __ldcg((const float4*)(hC + (j + 2) * 16));
            bhD[s] = __ldcg((const float4*)(hD + (j + 2) * 16));
        }
    }
}

// x span: 2 k16-blocks of the input stream (k-half of x's 64 columns).
__device__ __forceinline__ void xspan(float acc0[4][8],
                                      const uint4* __restrict__ px0,
                                      const float* __restrict__ pA, const float* __restrict__ pB,
                                      const float* __restrict__ pC, const float* __restrict__ pD) {
    float4 a0 = __ldcg((const float4*)pA), b0 = __ldcg((const float4*)pB);
    float4 c0 = __ldcg((const float4*)pC), d0 = __ldcg((const float4*)pD);
    float4 a1 = __ldcg((const float4*)(pA + 16)), b1 = __ldcg((const float4*)(pB + 16));
    float4 c1 = __ldcg((const float4*)(pC + 16)), d1 = __ldcg((const float4*)(pD + 16));
#pragma unroll
    for (int j = 0; j < 2; ++j) {
        uint4 q0 = px0[(0 * NK16_0 + j) * 32];
        uint4 q1 = px0[(1 * NK16_0 + j) * 32];
        uint4 q2 = px0[(2 * NK16_0 + j) * 32];
        uint4 q3 = px0[(3 * NK16_0 + j) * 32];
        Frag f = (j == 0) ? cvt_frag<true>(a0, b0, c0, d0)
                          : cvt_frag<true>(a1, b1, c1, d1);
        mma_gate(acc0[0], f, q0);
        mma_gate(acc0[1], f, q1);
        mma_gate(acc0[2], f, q2);
        mma_gate(acc0[3], f, q3);
    }
}

// ---- split-K exchange through smem: layout [i4][rt][lane] of float4 ---------
__device__ __forceinline__ void red_store(const float acc[4][8], float4* sred,
                                          int rt, int lane) {
    const float* a = &acc[0][0];
#pragma unroll
    for (int i4 = 0; i4 < 8; ++i4) {
        sred[i4 * 128 + rt * 32 + lane] =
            make_float4(a[i4 * 4 + 0], a[i4 * 4 + 1], a[i4 * 4 + 2], a[i4 * 4 + 3]);
    }
}

__device__ __forceinline__ void red_add(float acc[4][8], const float4* sred,
                                        int rt, int lane) {
    float* a = &acc[0][0];
#pragma unroll
    for (int i4 = 0; i4 < 8; ++i4) {
        float4 v = sred[i4 * 128 + rt * 32 + lane];
        a[i4 * 4 + 0] += v.x; a[i4 * 4 + 1] += v.y;
        a[i4 * 4 + 2] += v.z; a[i4 * 4 + 3] += v.w;
    }
}

// Same-slot swap: read peer's acc1 partial, overwrite slot with own acc0 partial.
__device__ __forceinline__ void red_swap(float acc1[4][8], const float acc0[4][8],
                                         float4* sred, int rt, int lane) {
    float* a1 = &acc1[0][0];
    const float* a0 = &acc0[0][0];
#pragma unroll
    for (int i4 = 0; i4 < 8; ++i4) {
        float4 v = sred[i4 * 128 + rt * 32 + lane];
        sred[i4 * 128 + rt * 32 + lane] =
            make_float4(a0[i4 * 4 + 0], a0[i4 * 4 + 1], a0[i4 * 4 + 2], a0[i4 * 4 + 3]);
        a1[i4 * 4 + 0] += v.x; a1[i4 * 4 + 1] += v.y;
        a1[i4 * 4 + 2] += v.z; a1[i4 * 4 + 3] += v.w;
    }
}

// rows4: global row indices; h stored pre-rounded to tf32.
__device__ __forceinline__ void cell_update(float acc[4][8],
                                            const float* __restrict__ bias8,
                                            float* __restrict__ creg,
                                            float* __restrict__ hout,
                                            const int* rows4, int cA) {
#pragma unroll
    for (int h = 0; h < 4; ++h) {
        int r = rows4[h];
        float2 hv;
#pragma unroll
        for (int q = 0; q < 2; ++q) {
            int p = h * 2 + q;
            float gi = acc[0][p] + bias8[0 + q];
            float gf = acc[1][p] + bias8[2 + q];
            float gg = acc[2][p] + bias8[4 + q];
            float go = acc[3][p] + bias8[6 + q];
            float cn = sigf(gf) * creg[p] + sigf(gi) * tanh_(gg);
            creg[p] = cn;
            float hv1 = sigf(go) * tanh_(cn);
            if (q == 0) hv.x = __uint_as_float(f2tf(hv1));
            else        hv.y = __uint_as_float(f2tf(hv1));
        }
        __stcg((float2*)&hout[r * HH + cA], hv);
    }
}

__global__ void __launch_bounds__(NTHREADS, 1)
lstm_kernel(const float* __restrict__ x, const float* __restrict__ y,
            const float* __restrict__ Wih0, const float* __restrict__ Whh0,
            const float* __restrict__ bih0, const float* __restrict__ bhh0,
            const float* __restrict__ Wih1, const float* __restrict__ Whh1,
            const float* __restrict__ bih1, const float* __restrict__ bhh1,
            const float* __restrict__ Wlin, const float* __restrict__ blin,
            float* __restrict__ dout, int out_size) {
    extern __shared__ uint4 smw[];
    uint4* sW0base = smw;
    uint4* sW1base = smw + SMEM_W0;
    float4* sred = (float4*)(smw + SMEM_W0 + SMEM_W1);

    const int tid = threadIdx.x;
    const int lane = tid & 31;
    const int w = tid >> 5;            // 0..7
    const int rt = w & 3;              // row tile 0..3
    const int kh = w >> 2;             // k-half 0..1
    const int grp = lane >> 2;
    const int tig = lane & 3;
    const int mtile = blockIdx.x >> 6; // 0..1
    const int cim = blockIdx.x & 63;   // CTA index within mtile cohort
    const int ub = cim;                // unit block 0..63
    const int m0 = mtile * 128;
    const int u0 = ub * 8;
    const int rA = m0 + rt * 32 + grp;
    const int cA = u0 + 2 * tig;
    const int rows4[4] = {rA, rA + 8, rA + 16, rA + 24};

    unsigned* barM = &g_barM[mtile * 32];

    // ------------- prologue: pack this CTA's weight slice into SMEM ---------
    for (int s = tid; s < SMEM_W0; s += NTHREADS) {
        int ln = s & 31;
        int kk = (s >> 5) % NK16_0;
        int g = s / (32 * NK16_0);
        int n = g * HH + u0 + (ln >> 2);
        int k = kk * 16 + (ln & 3) * 4;
        float v[4];
#pragma unroll
        for (int j = 0; j < 4; ++j) {
            int kj = k + j;
            v[j] = (kj < II) ? __ldg(&Wih0[n * II + kj]) : __ldg(&Whh0[n * HH + (kj - II)]);
        }
        sW0base[s] = make_uint4(f2tf(v[0]), f2tf(v[1]), f2tf(v[2]), f2tf(v[3]));
    }
    for (int s = tid; s < SMEM_W1; s += NTHREADS) {
        int ln = s & 31;
        int kk = (s >> 5) % NK16_1;
        int g = s / (32 * NK16_1);
        int n = g * HH + u0 + (ln >> 2);
        int k = kk * 16 + (ln & 3) * 4;
        float v[4];
#pragma unroll
        for (int j = 0; j < 4; ++j) {
            int kj = k + j;
            v[j] = (kj < HH) ? __ldg(&Wih1[n * HH + kj]) : __ldg(&Whh1[n * HH + (kj - HH)]);
        }
        sW1base[s] = make_uint4(f2tf(v[0]), f2tf(v[1]), f2tf(v[2]), f2tf(v[3]));
    }
    // zero own-mtile h1 init rows (cohort-local -> per-mtile barrier suffices)
    {
        float* z = g_h1[0] + (size_t)m0 * HH;
        for (int i = cim * NTHREADS + tid; i < 128 * HH; i += 64 * NTHREADS)
            z[i] = 0.0f;
    }

    // per-thread biases for the layer this half updates (kh=0: layer1, kh=1: layer0)
    float biasSel[8];
#pragma unroll
    for (int g = 0; g < 4; ++g)
#pragma unroll
        for (int q = 0; q < 2; ++q) {
            int n = g * HH + cA + q;
            biasSel[g * 2 + q] = kh ? (__ldg(&bih0[n]) + __ldg(&bhh0[n]))
                                    : (__ldg(&bih1[n]) + __ldg(&bhh1[n]));
        }

    // per-khalf block offsets
    const int hcolOff = kh * 256;
    const int wb_f1 = kh * 16;
    const int wb_f0 = 4 + kh * 16;
    const int wb_h1 = 32 + kh * 16;
    const int wb_x = kh * 2;
    const int xcolOff = kh * 32;

    const uint4* sW0 = sW0base + lane;
    const uint4* sW1 = sW1base + lane;
    const uint4* pW1f = sW1 + wb_f1 * 32;
    const uint4* pW0f = sW0 + wb_f0 * 32;
    const uint4* pW1h = sW1 + wb_h1 * 32;
    const uint4* px0  = sW0 + wb_x * 32;

    float* h0_cur = g_h0[1];
    float* h0_nxt = g_h0[0];
    float* h1_prv = g_h1[0];
    float* h1_cur = g_h1[1];

    float creg[8] = {0.f, 0.f, 0.f, 0.f, 0.f, 0.f, 0.f, 0.f};

    const int xoff = tig * 4;
    const float* xA = x + (size_t)rows4[0] * (TT * II) + xoff + xcolOff;
    const float* xB = x + (size_t)rows4[1] * (TT * II) + xoff + xcolOff;
    const float* xC = x + (size_t)rows4[2] * (TT * II) + xoff + xcolOff;
    const float* xD = x + (size_t)rows4[3] * (TT * II) + xoff + xcolOff;
    const int oA = rows4[0] * HH + xoff + hcolOff;
    const int oB = rows4[1] * HH + xoff + hcolOff;
    const int oC = rows4[2] * HH + xoff + hcolOff;
    const int oD = rows4[3] * HH + xoff + hcolOff;

    __syncthreads();   // weights + sred region visible intra-CTA

    float acc0[4][8];

    // ---- layer0(0): h0(0) = cell(x(0)); h-part is zero ----------------------
#pragma unroll
    for (int a = 0; a < 4; ++a)
#pragma unroll
        for (int b = 0; b < 8; ++b) acc0[a][b] = 0.0f;
    xspan(acc0, px0, xA, xB, xC, xD);
    if (kh == 0) red_store(acc0, sred, rt, lane);
    __syncthreads();
    if (kh == 1) {
        red_add(acc0, sred, rt, lane);
        cell_update(acc0, biasSel, creg, h0_cur, rows4, cA);
    }

    // ---- priming barrier; compute x(1) span inside the wait window ----------
    unsigned barn = 64;
    __threadfence();
    __syncthreads();
    if (tid == 0) atomicAdd(barM, 1u);
#pragma unroll
    for (int a = 0; a < 4; ++a)
#pragma unroll
        for (int b = 0; b < 8; ++b) acc0[a][b] = 0.0f;
    xspan(acc0, px0, xA + II, xB + II, xC + II, xD + II);
    if (tid == 0) {
        while (*(volatile unsigned*)barM < barn) {}
        __threadfence();
    }
    __syncthreads();

    // ---- main loop: iteration t computes layer1(t) and layer0(t+1) ----------
    // acc0 enters each iteration holding the x(t+1) contribution.
    for (int t = 0; t < TT; ++t) {
        float acc1[4][8];
#pragma unroll
        for (int a = 0; a < 4; ++a)
#pragma unroll
            for (int b = 0; b < 8; ++b) acc1[a][b] = 0.0f;

        merged_span(acc1, acc0, pW1f, pW0f, pW1h,
                    h0_cur + oA, h0_cur + oB, h0_cur + oC, h0_cur + oD,
                    h1_prv + oA, h1_prv + oB, h1_prv + oC, h1_prv + oD);

        // exchange: kh=1 sends acc1, kh=0 sends acc0 (same slots, two phases)
        if (kh == 1) red_store(acc1, sred, rt, lane);
        __syncthreads();
        if (kh == 0) red_swap(acc1, acc0, sred, rt, lane);
        __syncthreads();
        if (kh == 0) {
            cell_update(acc1, biasSel, creg, h1_cur, rows4, cA);
        } else {
            red_add(acc0, sred, rt, lane);
            cell_update(acc0, biasSel, creg, h0_nxt, rows4, cA);
        }

        if (t < TT - 1) {
            // arrive
            __threadfence();
            __syncthreads();
            if (tid == 0) atomicAdd(barM, 1u);
            // overlap: x(t+2) span into (dead) acc0
#pragma unroll
            for (int a = 0; a < 4; ++a)
#pragma unroll
                for (int b = 0; b < 8; ++b) acc0[a][b] = 0.0f;
            const int xt = (t + 2 < TT) ? (t + 2) : (TT - 1);
            xspan(acc0, px0, xA + xt * II, xB + xt * II, xC + xt * II, xD + xt * II);
            // wait
            barn += 64;
            if (tid == 0) {
                while (*(volatile unsigned*)barM < barn) {}
                __threadfence();
            }
            __syncthreads();
        }

        float* tmp = h0_cur; h0_cur = h0_nxt; h0_nxt = tmp;
        tmp = h1_prv; h1_prv = h1_cur; h1_cur = tmp;
    }

    // ---------------- final global barrier ----------------------------------
    __threadfence();
    __syncthreads();
    if (tid == 0) atomicAdd(&g_barF, 1u);
    if (blockIdx.x != 0) return;

    if (tid == 0) {
        while (*(volatile unsigned*)&g_barF < NCTA) {}
        __threadfence();
        g_barF = 0;          // reset for next graph replay
        g_barM[0] = 0;
        g_barM[32] = 0;
    }
    __syncthreads();

    // ---------------- epilogue on CTA 0: linear head + MSE loss --------------
    const float* h1fin = h1_prv;           // final h1 after last swap
    int b = tid;                           // 0..255 = batch row
    const float* hrow = h1fin + (size_t)b * HH;
    float s = __ldg(&blin[0]);
#pragma unroll 8
    for (int c2 = 0; c2 < HH; c2 += 4) {
        float4 wv = __ldg((const float4*)(Wlin + c2));
        float4 h4 = __ldcg((const float4*)(hrow + c2));
        s += h4.x * wv.x + h4.y * wv.y + h4.z * wv.z + h4.w * wv.w;
    }

    __shared__ float red[NTHREADS];
    float d = s - __ldg(&y[b]);
    red[b] = d * d;
    __syncthreads();
#pragma unroll
    for (int off = 128; off > 0; off >>= 1) {
        if (b < off) red[b] += red[b + off];
        __syncthreads();
    }
    float loss = red[0] * (1.0f / BATCH);

    if (out_size >= BATCH + 1) {
        dout[b] = s;
        if (b == 0) dout[BATCH] = loss;
        for (int i2 = BATCH + 1 + b; i2 < out_size; i2 += NTHREADS) dout[i2] = 0.0f;
    } else if (out_size == BATCH) {
        dout[b] = s;
    } else if (out_size == 1) {
        if (b == 0) dout[0] = loss;
    } else {
        if (b < out_size) dout[b] = (b < BATCH) ? s : loss;
    }
}

extern "C" void kernel_launch(void* const* d_in, const int* in_sizes, int n_in,
                              void* d_out, int out_size) {
    const float* x    = (const float*)d_in[0];
    const float* y    = (const float*)d_in[1];
    const float* Wih0 = (const float*)d_in[2];
    const float* Whh0 = (const float*)d_in[3];
    const float* bih0 = (const float*)d_in[4];
    const float* bhh0 = (const float*)d_in[5];
    const float* Wih1 = (const float*)d_in[6];
    const float* Whh1 = (const float*)d_in[7];
    const float* bih1 = (const float*)d_in[8];
    const float* bhh1 = (const float*)d_in[9];
    const float* Wlin = (const float*)d_in[10];
    const float* blin = (const float*)d_in[11];

    cudaFuncSetAttribute(lstm_kernel, cudaFuncAttributeMaxDynamicSharedMemorySize,
                         SMEM_BYTES);
    lstm_kernel<<<NCTA, NTHREADS, SMEM_BYTES>>>(x, y, Wih0, Whh0, bih0, bhh0,
                                                Wih1, Whh1, bih1, bhh1, Wlin, blin,
                                                (float*)d_out, out_size);
}